// round 1
// baseline (speedup 1.0000x reference)
#include <cuda_runtime.h>
#include <cuda_fp16.h>

// ---------------------------------------------------------------------------
// QLinear: fake-quantized linear layer.
//   1. min/max(weight) -> w_scale, w_zp ; min/max(x) -> x_scale, x_zp
//   2. qx' = clamp(round(x/xs + xzp),0,255)-128  (s8), qw = clamp(round(w/ws+wzp),-128,127) (s8)
//      e   = w - (qw - wzp)*ws   stored fp16  (|e| <= ws/2, tiny)
//   3. fused GEMM: iacc = qx' @ qw.T (exact, dp4a)   facc = qx' @ e.T (fp32 FFMA)
//      out_pre = xs*ws*(iacc - wzp*rsx - xzp'*rsw + K*xzp'*wzp) + bias   (exact int bracket)
//      act     = out_pre + xs*(facc - xzp'*rse)       -> global min/max (keys+atomics)
//   4. a_scale, a_zp from act min/max
//   5. requant d_out in place: (clamp(round(v/as+azp),0,255)-azp)*as
// ---------------------------------------------------------------------------

#define MAXM 8192
#define MAXN 4096
#define MAXK 4096

__device__ signed char g_qx[(size_t)MAXM * MAXK];
__device__ signed char g_qw[(size_t)MAXN * MAXK];
__device__ __half      g_e [(size_t)MAXN * MAXK];
__device__ int   g_rsx[MAXM];
__device__ int   g_rsw[MAXN];
__device__ float g_rse[MAXN];
__device__ unsigned g_keys[6];  // xmin,xmax,wmin,wmax,amin,amax (monotonic uint keys)
__device__ float g_xs, g_xzp, g_wsc, g_wzp, g_as, g_azp;
__device__ int   g_xzpi, g_wzpi;

__device__ __forceinline__ unsigned fkey(float v) {
    unsigned u = __float_as_uint(v);
    return (u & 0x80000000u) ? ~u : (u | 0x80000000u);
}
__device__ __forceinline__ float fdec(unsigned k) {
    unsigned u = (k & 0x80000000u) ? (k & 0x7FFFFFFFu) : ~k;
    return __uint_as_float(u);
}

__global__ void k_init() {
    if (threadIdx.x == 0) {
        g_keys[0] = 0xFFFFFFFFu; g_keys[1] = 0u;
        g_keys[2] = 0xFFFFFFFFu; g_keys[3] = 0u;
        g_keys[4] = 0xFFFFFFFFu; g_keys[5] = 0u;
    }
}

__global__ void k_minmax(const float* __restrict__ p, long long n4, int imin, int imax) {
    float lmin = __int_as_float(0x7f800000);
    float lmax = -lmin;
    const float4* p4 = (const float4*)p;
    for (long long i = blockIdx.x * (long long)blockDim.x + threadIdx.x; i < n4;
         i += (long long)gridDim.x * blockDim.x) {
        float4 v = p4[i];
        lmin = fminf(lmin, fminf(fminf(v.x, v.y), fminf(v.z, v.w)));
        lmax = fmaxf(lmax, fmaxf(fmaxf(v.x, v.y), fmaxf(v.z, v.w)));
    }
    #pragma unroll
    for (int o = 16; o > 0; o >>= 1) {
        lmin = fminf(lmin, __shfl_xor_sync(0xffffffffu, lmin, o));
        lmax = fmaxf(lmax, __shfl_xor_sync(0xffffffffu, lmax, o));
    }
    __shared__ float smin[8], smax[8];
    int w = threadIdx.x >> 5;
    if ((threadIdx.x & 31) == 0) { smin[w] = lmin; smax[w] = lmax; }
    __syncthreads();
    if (threadIdx.x == 0) {
        int nw = (int)(blockDim.x >> 5);
        for (int i = 1; i < nw; i++) { lmin = fminf(lmin, smin[i]); lmax = fmaxf(lmax, smax[i]); }
        atomicMin(&g_keys[imin], fkey(lmin));
        atomicMax(&g_keys[imax], fkey(lmax));
    }
}

__global__ void k_scales1() {
    float xmin = fdec(g_keys[0]), xmax = fdec(g_keys[1]);
    float wmin = fdec(g_keys[2]), wmax = fdec(g_keys[3]);
    float xs = (xmax - xmin) / 255.0f;
    float xzp = rintf(0.0f - xmin / xs);
    g_xs = xs; g_xzp = xzp; g_xzpi = (int)xzp - 128;
    float ws = (wmax - wmin) / 255.0f;
    float wzp = rintf(-128.0f - wmin / ws);
    g_wsc = ws; g_wzp = wzp; g_wzpi = (int)wzp;
}

__global__ void k_quant_x(const float* __restrict__ x, int K) {
    int row = blockIdx.x;
    const float* xr = x + (size_t)row * K;
    signed char* qr = g_qx + (size_t)row * K;
    float xs = g_xs, xzp = g_xzp;
    int sum = 0;
    for (int k = threadIdx.x * 4; k < K; k += blockDim.x * 4) {
        float4 v = *(const float4*)(xr + k);
        int q0 = (int)fminf(255.f, fmaxf(0.f, rintf(v.x / xs + xzp))) - 128;
        int q1 = (int)fminf(255.f, fmaxf(0.f, rintf(v.y / xs + xzp))) - 128;
        int q2 = (int)fminf(255.f, fmaxf(0.f, rintf(v.z / xs + xzp))) - 128;
        int q3 = (int)fminf(255.f, fmaxf(0.f, rintf(v.w / xs + xzp))) - 128;
        sum += q0 + q1 + q2 + q3;
        unsigned pk = (unsigned)(q0 & 0xFF) | ((unsigned)(q1 & 0xFF) << 8) |
                      ((unsigned)(q2 & 0xFF) << 16) | ((unsigned)(q3 & 0xFF) << 24);
        *(unsigned*)(qr + k) = pk;
    }
    #pragma unroll
    for (int o = 16; o > 0; o >>= 1) sum += __shfl_xor_sync(0xffffffffu, sum, o);
    __shared__ int ss[8];
    if ((threadIdx.x & 31) == 0) ss[threadIdx.x >> 5] = sum;
    __syncthreads();
    if (threadIdx.x == 0) {
        int t = 0; int nw = (int)(blockDim.x >> 5);
        for (int i = 0; i < nw; i++) t += ss[i];
        g_rsx[row] = t;
    }
}

__global__ void k_quant_w(const float* __restrict__ w, int K) {
    int row = blockIdx.x;
    const float* wr = w + (size_t)row * K;
    signed char* qr = g_qw + (size_t)row * K;
    __half* er = g_e + (size_t)row * K;
    float ws = g_wsc, wzp = g_wzp;
    int isum = 0; float fsum = 0.f;
    for (int k = threadIdx.x * 4; k < K; k += blockDim.x * 4) {
        float4 v = *(const float4*)(wr + k);
        float q0f = fminf(127.f, fmaxf(-128.f, rintf(v.x / ws + wzp)));
        float q1f = fminf(127.f, fmaxf(-128.f, rintf(v.y / ws + wzp)));
        float q2f = fminf(127.f, fmaxf(-128.f, rintf(v.z / ws + wzp)));
        float q3f = fminf(127.f, fmaxf(-128.f, rintf(v.w / ws + wzp)));
        int q0 = (int)q0f, q1 = (int)q1f, q2 = (int)q2f, q3 = (int)q3f;
        isum += q0 + q1 + q2 + q3;
        unsigned pk = (unsigned)(q0 & 0xFF) | ((unsigned)(q1 & 0xFF) << 8) |
                      ((unsigned)(q2 & 0xFF) << 16) | ((unsigned)(q3 & 0xFF) << 24);
        *(unsigned*)(qr + k) = pk;
        float e0 = v.x - (q0f - wzp) * ws;
        float e1 = v.y - (q1f - wzp) * ws;
        float e2 = v.z - (q2f - wzp) * ws;
        float e3 = v.w - (q3f - wzp) * ws;
        __half2 h01 = __floats2half2_rn(e0, e1);
        __half2 h23 = __floats2half2_rn(e2, e3);
        *(__half2*)(er + k)     = h01;
        *(__half2*)(er + k + 2) = h23;
        float2 b01 = __half22float2(h01), b23 = __half22float2(h23);
        fsum += (b01.x + b01.y) + (b23.x + b23.y);
    }
    #pragma unroll
    for (int o = 16; o > 0; o >>= 1) {
        isum += __shfl_xor_sync(0xffffffffu, isum, o);
        fsum += __shfl_xor_sync(0xffffffffu, fsum, o);
    }
    __shared__ int ss[8];
    __shared__ float fs[8];
    if ((threadIdx.x & 31) == 0) { ss[threadIdx.x >> 5] = isum; fs[threadIdx.x >> 5] = fsum; }
    __syncthreads();
    if (threadIdx.x == 0) {
        int ti = 0; float tf = 0.f; int nw = (int)(blockDim.x >> 5);
        for (int i = 0; i < nw; i++) { ti += ss[i]; tf += fs[i]; }
        g_rsw[row] = ti; g_rse[row] = tf;
    }
}

// Fused GEMM: 64x64 tile, 256 threads, 4x4 per thread. iacc via dp4a (exact),
// facc via FFMA on float(qx') * float(e_fp16). Epilogue computes out_pre (stored)
// and act (min/max reduced to global atomics).
__global__ void __launch_bounds__(256) k_gemm(const float* __restrict__ bias,
                                              float* __restrict__ out,
                                              int M, int N, int K) {
    __shared__ int    As4[64][8];
    __shared__ float  Asf[64][32];
    __shared__ int    Bq4[64][9];   // padded: kills 16-way conflicts
    __shared__ __half Be [64][36];  // padded: conflict-free half2 reads

    int tid = threadIdx.x;
    int tx = tid & 15, ty = tid >> 4;
    int row0 = blockIdx.y << 6, col0 = blockIdx.x << 6;

    int iacc[4][4];
    float facc[4][4];
    #pragma unroll
    for (int a = 0; a < 4; a++)
        #pragma unroll
        for (int b = 0; b < 4; b++) { iacc[a][b] = 0; facc[a][b] = 0.f; }

    for (int k0 = 0; k0 < K; k0 += 32) {
        #pragma unroll
        for (int u = 0; u < 2; u++) {
            int l = tid * 2 + u;
            int r = l >> 3, c = l & 7;
            int ap = *(const int*)(g_qx + (size_t)(row0 + r) * K + k0 + c * 4);
            As4[r][c] = ap;
            #pragma unroll
            for (int j = 0; j < 4; j++)
                Asf[r][c * 4 + j] = (float)((signed char)(ap >> (8 * j)));
            Bq4[r][c] = *(const int*)(g_qw + (size_t)(col0 + r) * K + k0 + c * 4);
        }
        {
            int r = tid >> 2, c8 = tid & 3;
            int4 ev = *(const int4*)(g_e + (size_t)(col0 + r) * K + k0 + c8 * 8);
            *(int2*)&Be[r][c8 * 8]     = make_int2(ev.x, ev.y);
            *(int2*)&Be[r][c8 * 8 + 4] = make_int2(ev.z, ev.w);
        }
        __syncthreads();

        #pragma unroll
        for (int c = 0; c < 8; c++) {
            int ap[4], bp[4];
            #pragma unroll
            for (int rt = 0; rt < 4; rt++) ap[rt] = As4[ty * 4 + rt][c];
            #pragma unroll
            for (int ct = 0; ct < 4; ct++) bp[ct] = Bq4[tx * 4 + ct][c];
            #pragma unroll
            for (int rt = 0; rt < 4; rt++)
                #pragma unroll
                for (int ct = 0; ct < 4; ct++)
                    iacc[rt][ct] = __dp4a(ap[rt], bp[ct], iacc[rt][ct]);

            float4 af[4], ef[4];
            #pragma unroll
            for (int rt = 0; rt < 4; rt++)
                af[rt] = *(const float4*)&Asf[ty * 4 + rt][c * 4];
            #pragma unroll
            for (int ct = 0; ct < 4; ct++) {
                uint2 t = *(const uint2*)&Be[tx * 4 + ct][c * 4];
                __half2 h0 = *reinterpret_cast<__half2*>(&t.x);
                __half2 h1 = *reinterpret_cast<__half2*>(&t.y);
                float2 f0 = __half22float2(h0), f1 = __half22float2(h1);
                ef[ct] = make_float4(f0.x, f0.y, f1.x, f1.y);
            }
            #pragma unroll
            for (int rt = 0; rt < 4; rt++)
                #pragma unroll
                for (int ct = 0; ct < 4; ct++) {
                    facc[rt][ct] = fmaf(af[rt].x, ef[ct].x, facc[rt][ct]);
                    facc[rt][ct] = fmaf(af[rt].y, ef[ct].y, facc[rt][ct]);
                    facc[rt][ct] = fmaf(af[rt].z, ef[ct].z, facc[rt][ct]);
                    facc[rt][ct] = fmaf(af[rt].w, ef[ct].w, facc[rt][ct]);
                }
        }
        __syncthreads();
    }

    // Epilogue: exact integer bracket -> out_pre; act = out_pre + xs*(facc - xzp'*rse)
    float xs = g_xs;
    float sxw = g_xs * g_wsc;
    int xzpi = g_xzpi, wzpi = g_wzpi;
    long long kzz = (long long)K * xzpi * wzpi;
    float amin = __int_as_float(0x7f800000), amax = -amin;

    int rsw_[4]; float rse_[4], bias_[4];
    #pragma unroll
    for (int ct = 0; ct < 4; ct++) {
        int gj = col0 + tx * 4 + ct;
        rsw_[ct] = g_rsw[gj]; rse_[ct] = g_rse[gj]; bias_[ct] = bias[gj];
    }
    #pragma unroll
    for (int rt = 0; rt < 4; rt++) {
        int gi = row0 + ty * 4 + rt;
        long long rsxi = (long long)wzpi * g_rsx[gi];
        float opv[4];
        #pragma unroll
        for (int ct = 0; ct < 4; ct++) {
            long long br = (long long)iacc[rt][ct] - rsxi - (long long)xzpi * rsw_[ct] + kzz;
            float op = (float)br * sxw + bias_[ct];
            float act = op + xs * (facc[rt][ct] - (float)xzpi * rse_[ct]);
            amin = fminf(amin, act);
            amax = fmaxf(amax, act);
            opv[ct] = op;
        }
        *(float4*)(out + (size_t)gi * N + col0 + tx * 4) =
            make_float4(opv[0], opv[1], opv[2], opv[3]);
    }

    #pragma unroll
    for (int o = 16; o > 0; o >>= 1) {
        amin = fminf(amin, __shfl_xor_sync(0xffffffffu, amin, o));
        amax = fmaxf(amax, __shfl_xor_sync(0xffffffffu, amax, o));
    }
    __shared__ float smin[8], smax[8];
    if ((tid & 31) == 0) { smin[tid >> 5] = amin; smax[tid >> 5] = amax; }
    __syncthreads();
    if (tid == 0) {
        for (int i = 1; i < 8; i++) { amin = fminf(amin, smin[i]); amax = fmaxf(amax, smax[i]); }
        atomicMin(&g_keys[4], fkey(amin));
        atomicMax(&g_keys[5], fkey(amax));
    }
}

__global__ void k_scales2() {
    float amin = fdec(g_keys[4]), amax = fdec(g_keys[5]);
    float as = (amax - amin) / 255.0f;
    g_as = as;
    g_azp = rintf(0.0f - amin / as);
}

__global__ void k_requant(float* __restrict__ out, long long n4) {
    float as = g_as, azp = g_azp;
    float4* p = (float4*)out;
    for (long long i = blockIdx.x * (long long)blockDim.x + threadIdx.x; i < n4;
         i += (long long)gridDim.x * blockDim.x) {
        float4 v = p[i];
        v.x = (fminf(255.f, fmaxf(0.f, rintf(v.x / as + azp))) - azp) * as;
        v.y = (fminf(255.f, fmaxf(0.f, rintf(v.y / as + azp))) - azp) * as;
        v.z = (fminf(255.f, fmaxf(0.f, rintf(v.z / as + azp))) - azp) * as;
        v.w = (fminf(255.f, fmaxf(0.f, rintf(v.w / as + azp))) - azp) * as;
        p[i] = v;
    }
}

extern "C" void kernel_launch(void* const* d_in, const int* in_sizes, int n_in,
                              void* d_out, int out_size) {
    const float* x = (const float*)d_in[0];
    const float* w = (const float*)d_in[1];
    const float* b = (const float*)d_in[2];
    float* out = (float*)d_out;

    int N = in_sizes[2];
    int K = in_sizes[1] / N;
    int M = in_sizes[0] / K;
    if (M > MAXM || N > MAXN || K > MAXK) return;

    k_init<<<1, 32>>>();
    k_minmax<<<864, 256>>>(x, (long long)M * K / 4, 0, 1);
    k_minmax<<<864, 256>>>(w, (long long)N * K / 4, 2, 3);
    k_scales1<<<1, 1>>>();
    k_quant_x<<<M, 256>>>(x, K);
    k_quant_w<<<N, 256>>>(w, K);
    dim3 grid(N / 64, M / 64);
    k_gemm<<<grid, 256>>>(b, out, M, N, K);
    k_scales2<<<1, 1>>>();
    k_requant<<<4096, 256>>>(out, (long long)M * N / 4);
}

// round 2
// speedup vs baseline: 2.4768x; 2.4768x over previous
#include <cuda_runtime.h>

// ---------------------------------------------------------------------------
// QLinear via exact dual-int8 tensor-core GEMM (mma.sync m16n8k32 s8):
//   qx' = clamp(round(x/xs+xzp),0,255)-128          (s8)
//   qw  = clamp(round(w/ws+wzp),-128,127)           (s8)
//   e   = w - (qw-wzp)*ws ;  qe = clamp(round(e/es),-127,127), es = ws/127 (s8)
//   GEMM1: iacc = qx' @ qw.T  (exact)   GEMM2: icor = qx' @ qe.T
//   out_pre = xs*ws*(iacc - wzp*rsx - xzp'*rsw + K*xzp'*wzp) + bias  (exact)
//   act     = out_pre + xs*es*(icor - xzp'*rsqe)  -> global min/max
//   requant in place with a_scale/a_zp.
// ---------------------------------------------------------------------------

#define MAXM 8192
#define MAXN 4096
#define MAXK 4096

__device__ signed char g_qx[(size_t)MAXM * MAXK];
__device__ signed char g_qw[(size_t)MAXN * MAXK];
__device__ signed char g_qe[(size_t)MAXN * MAXK];
__device__ int   g_rsx [MAXM];
__device__ int   g_rsw [MAXN];
__device__ int   g_rsqe[MAXN];
__device__ unsigned g_keys[6];  // xmin,xmax,wmin,wmax,amin,amax (monotonic keys)
__device__ float g_xs, g_xzp, g_wsc, g_wzp, g_es, g_as, g_azp;
__device__ int   g_xzpi, g_wzpi;

__device__ __forceinline__ unsigned fkey(float v) {
    unsigned u = __float_as_uint(v);
    return (u & 0x80000000u) ? ~u : (u | 0x80000000u);
}
__device__ __forceinline__ float fdec(unsigned k) {
    unsigned u = (k & 0x80000000u) ? (k & 0x7FFFFFFFu) : ~k;
    return __uint_as_float(u);
}

__global__ void k_init() {
    if (threadIdx.x == 0) {
        g_keys[0] = 0xFFFFFFFFu; g_keys[1] = 0u;
        g_keys[2] = 0xFFFFFFFFu; g_keys[3] = 0u;
        g_keys[4] = 0xFFFFFFFFu; g_keys[5] = 0u;
    }
}

__global__ void k_minmax(const float* __restrict__ p, long long n4, int imin, int imax) {
    float lmin = __int_as_float(0x7f800000);
    float lmax = -lmin;
    const float4* p4 = (const float4*)p;
    for (long long i = blockIdx.x * (long long)blockDim.x + threadIdx.x; i < n4;
         i += (long long)gridDim.x * blockDim.x) {
        float4 v = p4[i];
        lmin = fminf(lmin, fminf(fminf(v.x, v.y), fminf(v.z, v.w)));
        lmax = fmaxf(lmax, fmaxf(fmaxf(v.x, v.y), fmaxf(v.z, v.w)));
    }
    #pragma unroll
    for (int o = 16; o > 0; o >>= 1) {
        lmin = fminf(lmin, __shfl_xor_sync(0xffffffffu, lmin, o));
        lmax = fmaxf(lmax, __shfl_xor_sync(0xffffffffu, lmax, o));
    }
    __shared__ float smin[8], smax[8];
    int w = threadIdx.x >> 5;
    if ((threadIdx.x & 31) == 0) { smin[w] = lmin; smax[w] = lmax; }
    __syncthreads();
    if (threadIdx.x == 0) {
        int nw = (int)(blockDim.x >> 5);
        for (int i = 1; i < nw; i++) { lmin = fminf(lmin, smin[i]); lmax = fmaxf(lmax, smax[i]); }
        atomicMin(&g_keys[imin], fkey(lmin));
        atomicMax(&g_keys[imax], fkey(lmax));
    }
}

__global__ void k_scales1() {
    float xmin = fdec(g_keys[0]), xmax = fdec(g_keys[1]);
    float wmin = fdec(g_keys[2]), wmax = fdec(g_keys[3]);
    float xs = (xmax - xmin) / 255.0f;
    float xzp = rintf(0.0f - xmin / xs);
    g_xs = xs; g_xzp = xzp; g_xzpi = (int)xzp - 128;
    float ws = (wmax - wmin) / 255.0f;
    float wzp = rintf(-128.0f - wmin / ws);
    g_wsc = ws; g_wzp = wzp; g_wzpi = (int)wzp;
    g_es = ws / 127.0f;
}

__global__ void k_quant_x(const float* __restrict__ x, int K) {
    int row = blockIdx.x;
    const float* xr = x + (size_t)row * K;
    signed char* qr = g_qx + (size_t)row * K;
    float xs = g_xs, xzp = g_xzp;
    int sum = 0;
    for (int k = threadIdx.x * 4; k < K; k += blockDim.x * 4) {
        float4 v = *(const float4*)(xr + k);
        int q0 = (int)fminf(255.f, fmaxf(0.f, rintf(v.x / xs + xzp))) - 128;
        int q1 = (int)fminf(255.f, fmaxf(0.f, rintf(v.y / xs + xzp))) - 128;
        int q2 = (int)fminf(255.f, fmaxf(0.f, rintf(v.z / xs + xzp))) - 128;
        int q3 = (int)fminf(255.f, fmaxf(0.f, rintf(v.w / xs + xzp))) - 128;
        sum += q0 + q1 + q2 + q3;
        unsigned pk = (unsigned)(q0 & 0xFF) | ((unsigned)(q1 & 0xFF) << 8) |
                      ((unsigned)(q2 & 0xFF) << 16) | ((unsigned)(q3 & 0xFF) << 24);
        *(unsigned*)(qr + k) = pk;
    }
    #pragma unroll
    for (int o = 16; o > 0; o >>= 1) sum += __shfl_xor_sync(0xffffffffu, sum, o);
    __shared__ int ss[8];
    if ((threadIdx.x & 31) == 0) ss[threadIdx.x >> 5] = sum;
    __syncthreads();
    if (threadIdx.x == 0) {
        int t = 0; int nw = (int)(blockDim.x >> 5);
        for (int i = 0; i < nw; i++) t += ss[i];
        g_rsx[row] = t;
    }
}

__global__ void k_quant_w(const float* __restrict__ w, int K) {
    int row = blockIdx.x;
    const float* wr = w + (size_t)row * K;
    signed char* qr = g_qw + (size_t)row * K;
    signed char* er = g_qe + (size_t)row * K;
    float ws = g_wsc, wzp = g_wzp, es = g_es;
    int isum = 0, esum = 0;
    for (int k = threadIdx.x * 4; k < K; k += blockDim.x * 4) {
        float4 v = *(const float4*)(wr + k);
        float qf[4];
        qf[0] = fminf(127.f, fmaxf(-128.f, rintf(v.x / ws + wzp)));
        qf[1] = fminf(127.f, fmaxf(-128.f, rintf(v.y / ws + wzp)));
        qf[2] = fminf(127.f, fmaxf(-128.f, rintf(v.z / ws + wzp)));
        qf[3] = fminf(127.f, fmaxf(-128.f, rintf(v.w / ws + wzp)));
        float ev[4];
        ev[0] = v.x - (qf[0] - wzp) * ws;
        ev[1] = v.y - (qf[1] - wzp) * ws;
        ev[2] = v.z - (qf[2] - wzp) * ws;
        ev[3] = v.w - (qf[3] - wzp) * ws;
        int q[4], qe[4];
        #pragma unroll
        for (int j = 0; j < 4; j++) {
            q[j]  = (int)qf[j];
            qe[j] = (int)fminf(127.f, fmaxf(-127.f, rintf(ev[j] / es)));
            isum += q[j]; esum += qe[j];
        }
        unsigned pq = (unsigned)(q[0] & 0xFF) | ((unsigned)(q[1] & 0xFF) << 8) |
                      ((unsigned)(q[2] & 0xFF) << 16) | ((unsigned)(q[3] & 0xFF) << 24);
        unsigned pe = (unsigned)(qe[0] & 0xFF) | ((unsigned)(qe[1] & 0xFF) << 8) |
                      ((unsigned)(qe[2] & 0xFF) << 16) | ((unsigned)(qe[3] & 0xFF) << 24);
        *(unsigned*)(qr + k) = pq;
        *(unsigned*)(er + k) = pe;
    }
    #pragma unroll
    for (int o = 16; o > 0; o >>= 1) {
        isum += __shfl_xor_sync(0xffffffffu, isum, o);
        esum += __shfl_xor_sync(0xffffffffu, esum, o);
    }
    __shared__ int ss[8], se[8];
    if ((threadIdx.x & 31) == 0) { ss[threadIdx.x >> 5] = isum; se[threadIdx.x >> 5] = esum; }
    __syncthreads();
    if (threadIdx.x == 0) {
        int ti = 0, te = 0; int nw = (int)(blockDim.x >> 5);
        for (int i = 0; i < nw; i++) { ti += ss[i]; te += se[i]; }
        g_rsw[row] = ti; g_rsqe[row] = te;
    }
}

// ---------------------------------------------------------------------------
// Dual-int8 tensor-core GEMM. Block tile 128(M) x 64(N), K-step 64.
// 8 warps as 4(M) x 2(N); warp tile 32x32. cp.async double-buffered smem.
// Row stride 80B (20 words): fragment LDS conflict-free.
// ---------------------------------------------------------------------------
#define ASTRIDE 80

__device__ __forceinline__ void cpa16(void* smem, const void* gmem) {
    unsigned s = (unsigned)__cvta_generic_to_shared(smem);
    asm volatile("cp.async.cg.shared.global [%0], [%1], 16;\n" :: "r"(s), "l"(gmem));
}

__device__ __forceinline__ void mma_s8(int* d, const int* a, const int* b) {
    asm volatile(
        "mma.sync.aligned.m16n8k32.row.col.s32.s8.s8.s32 "
        "{%0,%1,%2,%3}, {%4,%5,%6,%7}, {%8,%9}, {%0,%1,%2,%3};\n"
        : "+r"(d[0]), "+r"(d[1]), "+r"(d[2]), "+r"(d[3])
        : "r"(a[0]), "r"(a[1]), "r"(a[2]), "r"(a[3]), "r"(b[0]), "r"(b[1]));
}

__global__ void __launch_bounds__(256) k_gemm(const float* __restrict__ bias,
                                              float* __restrict__ out,
                                              int M, int N, int K) {
    __shared__ __align__(16) signed char As[2][128 * ASTRIDE];
    __shared__ __align__(16) signed char Bw[2][64 * ASTRIDE];
    __shared__ __align__(16) signed char Be[2][64 * ASTRIDE];

    int tid = threadIdx.x;
    int wid = tid >> 5, lane = tid & 31;
    int wm = wid >> 1, wn = wid & 1;
    int g = lane >> 2, tig = lane & 3;
    int row0 = blockIdx.y << 7, col0 = blockIdx.x << 6;

    int acc1[2][4][4], acc2[2][4][4];
    #pragma unroll
    for (int i = 0; i < 2; i++)
        #pragma unroll
        for (int j = 0; j < 4; j++)
            #pragma unroll
            for (int c = 0; c < 4; c++) { acc1[i][j][c] = 0; acc2[i][j][c] = 0; }

    int nkt = K >> 6;

    // --- tile loader ---
    int a_r0 = tid >> 2, a_c = (tid & 3) * 16;     // A chunks: tid and tid+256
    int b_r  = tid >> 2, b_c = (tid & 3) * 16;     // B chunks: one each

    {   // prologue: tile 0 -> buf 0
        const signed char* gA = g_qx + (size_t)(row0 + a_r0) * K + a_c;
        cpa16(&As[0][a_r0 * ASTRIDE + a_c], gA);
        cpa16(&As[0][(a_r0 + 64) * ASTRIDE + a_c], gA + (size_t)64 * K);
        cpa16(&Bw[0][b_r * ASTRIDE + b_c], g_qw + (size_t)(col0 + b_r) * K + b_c);
        cpa16(&Be[0][b_r * ASTRIDE + b_c], g_qe + (size_t)(col0 + b_r) * K + b_c);
        asm volatile("cp.async.commit_group;\n");
    }

    #pragma unroll 1
    for (int kt = 0; kt < nkt; kt++) {
        asm volatile("cp.async.wait_group 0;\n");
        __syncthreads();

        if (kt + 1 < nkt) {
            int b = (kt + 1) & 1;
            int k0 = (kt + 1) << 6;
            const signed char* gA = g_qx + (size_t)(row0 + a_r0) * K + k0 + a_c;
            cpa16(&As[b][a_r0 * ASTRIDE + a_c], gA);
            cpa16(&As[b][(a_r0 + 64) * ASTRIDE + a_c], gA + (size_t)64 * K);
            cpa16(&Bw[b][b_r * ASTRIDE + b_c], g_qw + (size_t)(col0 + b_r) * K + k0 + b_c);
            cpa16(&Be[b][b_r * ASTRIDE + b_c], g_qe + (size_t)(col0 + b_r) * K + k0 + b_c);
            asm volatile("cp.async.commit_group;\n");
        }

        const signed char* Ab  = As[kt & 1];
        const signed char* Bwb = Bw[kt & 1];
        const signed char* Beb = Be[kt & 1];

        #pragma unroll
        for (int kseg = 0; kseg < 2; kseg++) {
            int koff = kseg * 32 + tig * 4;
            int a[2][4];
            #pragma unroll
            for (int mi = 0; mi < 2; mi++) {
                int r0 = wm * 32 + mi * 16 + g;
                a[mi][0] = *(const int*)&Ab[r0 * ASTRIDE + koff];
                a[mi][1] = *(const int*)&Ab[(r0 + 8) * ASTRIDE + koff];
                a[mi][2] = *(const int*)&Ab[r0 * ASTRIDE + koff + 16];
                a[mi][3] = *(const int*)&Ab[(r0 + 8) * ASTRIDE + koff + 16];
            }
            int bw[4][2], be2[4][2];
            #pragma unroll
            for (int ni = 0; ni < 4; ni++) {
                int rn = wn * 32 + ni * 8 + g;
                bw[ni][0]  = *(const int*)&Bwb[rn * ASTRIDE + koff];
                bw[ni][1]  = *(const int*)&Bwb[rn * ASTRIDE + koff + 16];
                be2[ni][0] = *(const int*)&Beb[rn * ASTRIDE + koff];
                be2[ni][1] = *(const int*)&Beb[rn * ASTRIDE + koff + 16];
            }
            #pragma unroll
            for (int mi = 0; mi < 2; mi++)
                #pragma unroll
                for (int ni = 0; ni < 4; ni++) {
                    mma_s8(acc1[mi][ni], a[mi], bw[ni]);
                    mma_s8(acc2[mi][ni], a[mi], be2[ni]);
                }
        }
        __syncthreads();
    }

    // --- epilogue: exact bracket -> out_pre; act min/max ---
    float xs = g_xs;
    float sxw = g_xs * g_wsc;
    float ce  = g_xs * g_es;
    int xzpi = g_xzpi, wzpi = g_wzpi;
    long long kzz = (long long)K * xzpi * wzpi;
    float amin = __int_as_float(0x7f800000), amax = -amin;

    int   rsw_[4][2], rsqe_[4][2];
    float bias_[4][2];
    int cbase[4];
    #pragma unroll
    for (int ni = 0; ni < 4; ni++) {
        int c0 = col0 + wn * 32 + ni * 8 + tig * 2;
        cbase[ni] = c0;
        rsw_[ni][0] = g_rsw[c0];  rsw_[ni][1] = g_rsw[c0 + 1];
        rsqe_[ni][0] = g_rsqe[c0]; rsqe_[ni][1] = g_rsqe[c0 + 1];
        float2 bv = *(const float2*)(bias + c0);
        bias_[ni][0] = bv.x; bias_[ni][1] = bv.y;
    }

    #pragma unroll
    for (int mi = 0; mi < 2; mi++) {
        #pragma unroll
        for (int rr = 0; rr < 2; rr++) {
            int row = row0 + wm * 32 + mi * 16 + rr * 8 + g;
            long long rowc = (long long)wzpi * g_rsx[row] - kzz;
            #pragma unroll
            for (int ni = 0; ni < 4; ni++) {
                float ov[2];
                #pragma unroll
                for (int cc = 0; cc < 2; cc++) {
                    int v1 = acc1[mi][ni][rr * 2 + cc];
                    int v2 = acc2[mi][ni][rr * 2 + cc];
                    long long br = (long long)v1 - rowc - (long long)xzpi * rsw_[ni][cc];
                    float op = (float)br * sxw + bias_[ni][cc];
                    float corr = ce * (float)((long long)v2 - (long long)xzpi * rsqe_[ni][cc]);
                    float act = op + corr;
                    amin = fminf(amin, act);
                    amax = fmaxf(amax, act);
                    ov[cc] = op;
                }
                *(float2*)(out + (size_t)row * N + cbase[ni]) = make_float2(ov[0], ov[1]);
            }
        }
    }

    #pragma unroll
    for (int o = 16; o > 0; o >>= 1) {
        amin = fminf(amin, __shfl_xor_sync(0xffffffffu, amin, o));
        amax = fmaxf(amax, __shfl_xor_sync(0xffffffffu, amax, o));
    }
    __shared__ float smin[8], smax[8];
    if (lane == 0) { smin[wid] = amin; smax[wid] = amax; }
    __syncthreads();
    if (tid == 0) {
        #pragma unroll
        for (int i = 1; i < 8; i++) { amin = fminf(amin, smin[i]); amax = fmaxf(amax, smax[i]); }
        atomicMin(&g_keys[4], fkey(amin));
        atomicMax(&g_keys[5], fkey(amax));
    }
}

__global__ void k_scales2() {
    float amin = fdec(g_keys[4]), amax = fdec(g_keys[5]);
    float as = (amax - amin) / 255.0f;
    g_as = as;
    g_azp = rintf(0.0f - amin / as);
}

__global__ void k_requant(float* __restrict__ out, long long n4) {
    float as = g_as, azp = g_azp;
    float4* p = (float4*)out;
    for (long long i = blockIdx.x * (long long)blockDim.x + threadIdx.x; i < n4;
         i += (long long)gridDim.x * blockDim.x) {
        float4 v = p[i];
        v.x = (fminf(255.f, fmaxf(0.f, rintf(v.x / as + azp))) - azp) * as;
        v.y = (fminf(255.f, fmaxf(0.f, rintf(v.y / as + azp))) - azp) * as;
        v.z = (fminf(255.f, fmaxf(0.f, rintf(v.z / as + azp))) - azp) * as;
        v.w = (fminf(255.f, fmaxf(0.f, rintf(v.w / as + azp))) - azp) * as;
        p[i] = v;
    }
}

extern "C" void kernel_launch(void* const* d_in, const int* in_sizes, int n_in,
                              void* d_out, int out_size) {
    const float* x = (const float*)d_in[0];
    const float* w = (const float*)d_in[1];
    const float* b = (const float*)d_in[2];
    float* out = (float*)d_out;

    int N = in_sizes[2];
    int K = in_sizes[1] / N;
    int M = in_sizes[0] / K;
    if (M > MAXM || N > MAXN || K > MAXK) return;

    k_init<<<1, 32>>>();
    k_minmax<<<864, 256>>>(x, (long long)M * K / 4, 0, 1);
    k_minmax<<<864, 256>>>(w, (long long)N * K / 4, 2, 3);
    k_scales1<<<1, 1>>>();
    k_quant_x<<<M, 256>>>(x, K);
    k_quant_w<<<N, 256>>>(w, K);
    dim3 grid(N / 64, M / 128);
    k_gemm<<<grid, 256>>>(b, out, M, N, K);
    k_scales2<<<1, 1>>>();
    k_requant<<<4096, 256>>>(out, (long long)M * N / 4);
}

// round 6
// speedup vs baseline: 15.6989x; 6.3384x over previous
#include <cuda_runtime.h>
#include <cuda_bf16.h>
#include <cstdint>

// ---------------------------------------------------------------------------
// QLinear via exact dual GEMM on integer lattices.
//   qx' = clamp(round(x/xs+xzp),0,255)-128 ; qw = clamp(round(w/ws+wzp),-128,127)
//   qe  = round((w - (qw-wzp)*ws)/es), es = ws/127
//   GEMM1: qx'@qw.T (exact bracket -> out_pre)  GEMM2: qx'@qe.T (act correction)
//   act min/max -> a_scale/a_zp -> requant in place.
//
// Engines (compile-time per gencode pass):
//   k_gemm_tc : tcgen05 kind::f16 on bf16-encoded integers (sm_103a pass).
//               NOTE: zero static __shared__ in this kernel — dynamic smem
//               must be 1024B-aligned for SW128 tiles/descriptors.
//   k_gemm_fb : mma.sync s8 fallback (baseline compute_103 pass).
// ---------------------------------------------------------------------------

#if defined(__CUDA_ARCH__) && (__CUDA_ARCH__ == 1030) && \
    (defined(__CUDA_ARCH_FEAT_SM103_ALL) || \
     (defined(__CUDA_ARCH_SPECIFIC__) && (__CUDA_ARCH_SPECIFIC__ == 1030)) || \
     (defined(__CUDA_ARCH_FAMILY_SPECIFIC__) && (__CUDA_ARCH_FAMILY_SPECIFIC__ == 1030)))
#define HAVE_TC 1
#else
#define HAVE_TC 0
#endif

#define MAXM 8192
#define MAXN 4096
#define MAXK 4096

__device__ signed char    g_qx [(size_t)MAXM * MAXK];
__device__ signed char    g_qw [(size_t)MAXN * MAXK];
__device__ signed char    g_qe [(size_t)MAXN * MAXK];
__device__ __nv_bfloat16  g_qxh[(size_t)MAXM * MAXK];
__device__ __nv_bfloat16  g_qwh[(size_t)MAXN * MAXK];
__device__ __nv_bfloat16  g_qeh[(size_t)MAXN * MAXK];
__device__ int   g_rsx [MAXM];
__device__ int   g_rsw [MAXN];
__device__ int   g_rsqe[MAXN];
__device__ unsigned g_keys[6];
__device__ float g_xs, g_xzp, g_wsc, g_wzp, g_es, g_as, g_azp;
__device__ int   g_xzpi, g_wzpi;

__device__ __forceinline__ unsigned fkey(float v) {
    unsigned u = __float_as_uint(v);
    return (u & 0x80000000u) ? ~u : (u | 0x80000000u);
}
__device__ __forceinline__ float fdec(unsigned k) {
    unsigned u = (k & 0x80000000u) ? (k & 0x7FFFFFFFu) : ~k;
    return __uint_as_float(u);
}

__device__ __forceinline__ void cpa16(uint32_t sdst, const void* g) {
    asm volatile("cp.async.cg.shared.global [%0], [%1], 16;" :: "r"(sdst), "l"(g));
}
#define SWZ(o) ((unsigned)(o) ^ ((((unsigned)(o)) >> 3) & 0x70u))

// ---- prologue kernels -------------------------------------------------------
__global__ void k_init() {
    if (threadIdx.x == 0) {
        g_keys[0] = 0xFFFFFFFFu; g_keys[1] = 0u;
        g_keys[2] = 0xFFFFFFFFu; g_keys[3] = 0u;
        g_keys[4] = 0xFFFFFFFFu; g_keys[5] = 0u;
    }
}

__global__ void k_minmax(const float* __restrict__ p, long long n4, int imin, int imax) {
    float lmin = __int_as_float(0x7f800000);
    float lmax = -lmin;
    const float4* p4 = (const float4*)p;
    for (long long i = blockIdx.x * (long long)blockDim.x + threadIdx.x; i < n4;
         i += (long long)gridDim.x * blockDim.x) {
        float4 v = p4[i];
        lmin = fminf(lmin, fminf(fminf(v.x, v.y), fminf(v.z, v.w)));
        lmax = fmaxf(lmax, fmaxf(fmaxf(v.x, v.y), fmaxf(v.z, v.w)));
    }
    #pragma unroll
    for (int o = 16; o > 0; o >>= 1) {
        lmin = fminf(lmin, __shfl_xor_sync(0xffffffffu, lmin, o));
        lmax = fmaxf(lmax, __shfl_xor_sync(0xffffffffu, lmax, o));
    }
    __shared__ float smin[8], smax[8];
    int w = threadIdx.x >> 5;
    if ((threadIdx.x & 31) == 0) { smin[w] = lmin; smax[w] = lmax; }
    __syncthreads();
    if (threadIdx.x == 0) {
        int nw = (int)(blockDim.x >> 5);
        for (int i = 1; i < nw; i++) { lmin = fminf(lmin, smin[i]); lmax = fmaxf(lmax, smax[i]); }
        atomicMin(&g_keys[imin], fkey(lmin));
        atomicMax(&g_keys[imax], fkey(lmax));
    }
}

__global__ void k_scales1() {
    float xmin = fdec(g_keys[0]), xmax = fdec(g_keys[1]);
    float wmin = fdec(g_keys[2]), wmax = fdec(g_keys[3]);
    float xs = (xmax - xmin) / 255.0f;
    float xzp = rintf(0.0f - xmin / xs);
    g_xs = xs; g_xzp = xzp; g_xzpi = (int)xzp - 128;
    float ws = (wmax - wmin) / 255.0f;
    float wzp = rintf(-128.0f - wmin / ws);
    g_wsc = ws; g_wzp = wzp; g_wzpi = (int)wzp;
    g_es = ws / 127.0f;
}

__global__ void k_quant_x(const float* __restrict__ x, int K) {
    int row = blockIdx.x;
    const float* xr = x + (size_t)row * K;
    signed char* qr = g_qx + (size_t)row * K;
    __nv_bfloat16* hr = g_qxh + (size_t)row * K;
    float xs = g_xs, xzp = g_xzp;
    int sum = 0;
    for (int k = threadIdx.x * 4; k < K; k += blockDim.x * 4) {
        float4 v = *(const float4*)(xr + k);
        int q0 = (int)fminf(255.f, fmaxf(0.f, rintf(v.x / xs + xzp))) - 128;
        int q1 = (int)fminf(255.f, fmaxf(0.f, rintf(v.y / xs + xzp))) - 128;
        int q2 = (int)fminf(255.f, fmaxf(0.f, rintf(v.z / xs + xzp))) - 128;
        int q3 = (int)fminf(255.f, fmaxf(0.f, rintf(v.w / xs + xzp))) - 128;
        sum += q0 + q1 + q2 + q3;
        unsigned pk = (unsigned)(q0 & 0xFF) | ((unsigned)(q1 & 0xFF) << 8) |
                      ((unsigned)(q2 & 0xFF) << 16) | ((unsigned)(q3 & 0xFF) << 24);
        *(unsigned*)(qr + k) = pk;
        __nv_bfloat162 h01 = __floats2bfloat162_rn((float)q0, (float)q1);  // exact
        __nv_bfloat162 h23 = __floats2bfloat162_rn((float)q2, (float)q3);
        *(__nv_bfloat162*)(hr + k)     = h01;
        *(__nv_bfloat162*)(hr + k + 2) = h23;
    }
    #pragma unroll
    for (int o = 16; o > 0; o >>= 1) sum += __shfl_xor_sync(0xffffffffu, sum, o);
    __shared__ int ss[8];
    if ((threadIdx.x & 31) == 0) ss[threadIdx.x >> 5] = sum;
    __syncthreads();
    if (threadIdx.x == 0) {
        int t = 0; int nw = (int)(blockDim.x >> 5);
        for (int i = 0; i < nw; i++) t += ss[i];
        g_rsx[row] = t;
    }
}

__global__ void k_quant_w(const float* __restrict__ w, int K) {
    int row = blockIdx.x;
    const float* wr = w + (size_t)row * K;
    signed char* qr = g_qw + (size_t)row * K;
    signed char* er = g_qe + (size_t)row * K;
    __nv_bfloat16* qh = g_qwh + (size_t)row * K;
    __nv_bfloat16* eh = g_qeh + (size_t)row * K;
    float ws = g_wsc, wzp = g_wzp, es = g_es;
    int isum = 0, esum = 0;
    for (int k = threadIdx.x * 4; k < K; k += blockDim.x * 4) {
        float4 v = *(const float4*)(wr + k);
        float qf[4];
        qf[0] = fminf(127.f, fmaxf(-128.f, rintf(v.x / ws + wzp)));
        qf[1] = fminf(127.f, fmaxf(-128.f, rintf(v.y / ws + wzp)));
        qf[2] = fminf(127.f, fmaxf(-128.f, rintf(v.z / ws + wzp)));
        qf[3] = fminf(127.f, fmaxf(-128.f, rintf(v.w / ws + wzp)));
        float ev[4];
        ev[0] = v.x - (qf[0] - wzp) * ws;
        ev[1] = v.y - (qf[1] - wzp) * ws;
        ev[2] = v.z - (qf[2] - wzp) * ws;
        ev[3] = v.w - (qf[3] - wzp) * ws;
        int q[4], qe[4];
        #pragma unroll
        for (int j = 0; j < 4; j++) {
            q[j]  = (int)qf[j];
            qe[j] = (int)fminf(127.f, fmaxf(-127.f, rintf(ev[j] / es)));
            isum += q[j]; esum += qe[j];
        }
        unsigned pq = (unsigned)(q[0] & 0xFF) | ((unsigned)(q[1] & 0xFF) << 8) |
                      ((unsigned)(q[2] & 0xFF) << 16) | ((unsigned)(q[3] & 0xFF) << 24);
        unsigned pe = (unsigned)(qe[0] & 0xFF) | ((unsigned)(qe[1] & 0xFF) << 8) |
                      ((unsigned)(qe[2] & 0xFF) << 16) | ((unsigned)(qe[3] & 0xFF) << 24);
        *(unsigned*)(qr + k) = pq;
        *(unsigned*)(er + k) = pe;
        *(__nv_bfloat162*)(qh + k)     = __floats2bfloat162_rn((float)q[0], (float)q[1]);
        *(__nv_bfloat162*)(qh + k + 2) = __floats2bfloat162_rn((float)q[2], (float)q[3]);
        *(__nv_bfloat162*)(eh + k)     = __floats2bfloat162_rn((float)qe[0], (float)qe[1]);
        *(__nv_bfloat162*)(eh + k + 2) = __floats2bfloat162_rn((float)qe[2], (float)qe[3]);
    }
    #pragma unroll
    for (int o = 16; o > 0; o >>= 1) {
        isum += __shfl_xor_sync(0xffffffffu, isum, o);
        esum += __shfl_xor_sync(0xffffffffu, esum, o);
    }
    __shared__ int ss[8], se[8];
    if ((threadIdx.x & 31) == 0) { ss[threadIdx.x >> 5] = isum; se[threadIdx.x >> 5] = esum; }
    __syncthreads();
    if (threadIdx.x == 0) {
        int ti = 0, te = 0; int nw = (int)(blockDim.x >> 5);
        for (int i = 0; i < nw; i++) { ti += ss[i]; te += se[i]; }
        g_rsw[row] = ti; g_rsqe[row] = te;
    }
}

// ===========================================================================
// Engine A: tcgen05 kind::f16 (bf16 ints), arch-specific pass only.
// CTA tile 256(M) x 128(N), K staged 64 (128B bf16 rows), 3-stage cp.async.
// TMEM: D1a@0, D1b@128, D2a@256, D2b@384 (512 f32 cols).
// Stage 64KB: A(256x128B)@0 [atoms @0,@16K], Bw(128x128B)@32K, Be@48K.
// Dynamic smem header (1024B): tmem-ptr@0, mbarriers@8..47, reduce@64..191.
// ===========================================================================
#define STAGES      3
#define STAGE_BYTES 65536
#define TILE_BASE   1024
#define SMEM_TC     (TILE_BASE + STAGES * STAGE_BYTES)

#if HAVE_TC
#define MBAR_INIT(addr, cnt) \
    asm volatile("mbarrier.init.shared.b64 [%0], %1;" :: "r"(addr), "r"(cnt) : "memory")

#define MBAR_WAIT(addr, ph) do {                                              \
    unsigned _m = (addr), _p = (ph), _d;                                      \
    asm volatile("{\n\t.reg .pred p;\n\t"                                     \
        "mbarrier.try_wait.parity.acquire.cta.shared::cta.b64 p, [%1], %2;\n\t" \
        "selp.b32 %0, 1, 0, p;\n\t}" : "=r"(_d) : "r"(_m), "r"(_p) : "memory"); \
    if (!_d) {                                                                \
        asm volatile("{\n\t.reg .pred P1;\n\t"                                \
            "W%=:\n\t"                                                        \
            "mbarrier.try_wait.parity.acquire.cta.shared::cta.b64 P1, [%0], %1, 0x989680;\n\t" \
            "@P1 bra.uni D%=;\n\t"                                            \
            "bra.uni W%=;\n\t"                                                \
            "D%=:\n\t}" :: "r"(_m), "r"(_p) : "memory");                      \
    }                                                                         \
} while (0)

#define TC_COMMIT(addr) \
    asm volatile("tcgen05.commit.cta_group::1.mbarrier::arrive::one.shared::cluster.b64 [%0];" \
                 :: "r"(addr) : "memory")

#define LDTM_X32(r, a) \
    asm volatile("tcgen05.ld.sync.aligned.32x32b.x32.b32 " \
        "{%0,%1,%2,%3,%4,%5,%6,%7,%8,%9,%10,%11,%12,%13,%14,%15," \
        "%16,%17,%18,%19,%20,%21,%22,%23,%24,%25,%26,%27,%28,%29,%30,%31}, [%32];" \
        : "=r"((r)[0]),"=r"((r)[1]),"=r"((r)[2]),"=r"((r)[3]),"=r"((r)[4]),"=r"((r)[5]), \
          "=r"((r)[6]),"=r"((r)[7]),"=r"((r)[8]),"=r"((r)[9]),"=r"((r)[10]),"=r"((r)[11]), \
          "=r"((r)[12]),"=r"((r)[13]),"=r"((r)[14]),"=r"((r)[15]),"=r"((r)[16]),"=r"((r)[17]), \
          "=r"((r)[18]),"=r"((r)[19]),"=r"((r)[20]),"=r"((r)[21]),"=r"((r)[22]),"=r"((r)[23]), \
          "=r"((r)[24]),"=r"((r)[25]),"=r"((r)[26]),"=r"((r)[27]),"=r"((r)[28]),"=r"((r)[29]), \
          "=r"((r)[30]),"=r"((r)[31]) : "r"(a))

static __device__ __forceinline__ uint64_t mkdesc(uint32_t addr) {
    uint64_t d = ((uint64_t)2 << 61) | ((uint64_t)1 << 46) |
                 ((uint64_t)64 << 32) | ((uint64_t)1 << 16);
    return d | ((uint64_t)(addr >> 4) & 0x3FFF);
}

// SS-mode bf16 MMA, fp32 accum: idesc = F32 | BF16 x BF16 | N=128 | M=128
__device__ __forceinline__ void mma_bf16(uint32_t d, uint64_t a, uint64_t b,
                                         uint32_t idesc, unsigned en) {
    uint32_t z = 0;
    asm volatile(
        "{\n\t.reg .pred p;\n\t"
        "setp.ne.u32 p, %5, 0;\n\t"
        "tcgen05.mma.cta_group::1.kind::f16 [%0], %1, %2, %3, {%4, %4, %4, %4}, p;\n\t}"
        :: "r"(d), "l"(a), "l"(b), "r"(idesc), "r"(z), "r"(en) : "memory");
}

// k0 in K-elements (multiple of 64). bf16 rows: 128 bytes per 64 elems.
__device__ __forceinline__ void load_stage(uint32_t sbase, int row0, int col0,
                                           int k0, int K, int tid) {
    const int coli = (tid & 7) << 4;
    const int r0 = tid >> 3;
    const size_t rstride = (size_t)K * 2;
    const char* gA = (const char*)g_qxh + ((size_t)(row0 + r0) * K + k0) * 2 + coli;
    #pragma unroll
    for (int i = 0; i < 8; i++)
        cpa16(sbase + SWZ((r0 + i * 32) * 128 + coli), gA + (size_t)(i * 32) * rstride);
    const char* gBw = (const char*)g_qwh + ((size_t)(col0 + r0) * K + k0) * 2 + coli;
    const char* gBe = (const char*)g_qeh + ((size_t)(col0 + r0) * K + k0) * 2 + coli;
    #pragma unroll
    for (int i = 0; i < 4; i++) {
        unsigned so = SWZ((r0 + i * 32) * 128 + coli);
        cpa16(sbase + 32768u + so, gBw + (size_t)(i * 32) * rstride);
        cpa16(sbase + 49152u + so, gBe + (size_t)(i * 32) * rstride);
    }
}
#endif  // HAVE_TC

__global__ void __launch_bounds__(256, 1) k_gemm_tc(const float* __restrict__ bias,
                                                    float* __restrict__ out,
                                                    int M, int N, int K) {
#if HAVE_TC
    extern __shared__ char smem[];   // ZERO static smem in this kernel (SW128 needs 1024B-aligned base)
    uint32_t sb = (uint32_t)__cvta_generic_to_shared(smem);
    float* red_min = (float*)(smem + 64);   // 8 floats
    float* red_max = (float*)(smem + 96);   // 8 floats
    int tid = threadIdx.x, wid = tid >> 5, lane = tid & 31;
    int row0 = blockIdx.y << 8, col0 = blockIdx.x << 7;
    int nkt = K >> 6;

    if (wid == 0) {
        uint32_t nc = 512;
        asm volatile("tcgen05.alloc.cta_group::1.sync.aligned.shared::cta.b32 [%0], %1;"
                     :: "r"(sb), "r"(nc) : "memory");
        asm volatile("tcgen05.relinquish_alloc_permit.cta_group::1.sync.aligned;");
    }
    if (tid == 0) {
        #pragma unroll
        for (int s = 0; s < STAGES; s++) MBAR_INIT(sb + 8 + 8 * s, 1);
        MBAR_INIT(sb + 8 + 8 * STAGES, 1);
    }
    __syncthreads();
    uint32_t tb;
    asm volatile("ld.shared.b32 %0, [%1];" : "=r"(tb) : "r"(sb));

    #pragma unroll
    for (int s = 0; s < STAGES; s++) {
        if (s < nkt) load_stage(sb + TILE_BASE + s * STAGE_BYTES, row0, col0, s << 6, K, tid);
        asm volatile("cp.async.commit_group;" ::: "memory");
    }

    const uint32_t IDESC = (1u << 4) | (1u << 7) | (1u << 10) |
                           (16u << 17) | (8u << 24);   // F32, bf16 x bf16, N=128, M=128
    uint32_t dbar = sb + 8 + 8 * STAGES;

    for (int kt = 0; kt < nkt; kt++) {
        int b = kt % STAGES;
        asm volatile("cp.async.wait_group 2;" ::: "memory");
        __syncthreads();

        if (tid == 0) {
            asm volatile("fence.proxy.async.shared::cta;" ::: "memory");
            uint32_t sbase = sb + TILE_BASE + b * STAGE_BYTES;
            uint64_t dAa = mkdesc(sbase);
            uint64_t dAb = mkdesc(sbase + 16384u);
            uint64_t dBw = mkdesc(sbase + 32768u);
            uint64_t dBe = mkdesc(sbase + 49152u);
            #pragma unroll
            for (int k = 0; k < 4; k++) {   // 4 K-steps of 16 bf16 (32B = +2 desc units)
                unsigned en = (kt > 0 || k > 0) ? 1u : 0u;
                mma_bf16(tb + 0,   dAa + k * 2, dBw + k * 2, IDESC, en);
                mma_bf16(tb + 128, dAb + k * 2, dBw + k * 2, IDESC, en);
                mma_bf16(tb + 256, dAa + k * 2, dBe + k * 2, IDESC, en);
                mma_bf16(tb + 384, dAb + k * 2, dBe + k * 2, IDESC, en);
            }
            TC_COMMIT(sb + 8 + 8 * b);
            if (kt == nkt - 1) TC_COMMIT(dbar);
        }

        if (kt + STAGES < nkt) {
            MBAR_WAIT(sb + 8 + 8 * b, (unsigned)((kt / STAGES) & 1));
            load_stage(sb + TILE_BASE + b * STAGE_BYTES, row0, col0,
                       (kt + STAGES) << 6, K, tid);
        }
        asm volatile("cp.async.commit_group;" ::: "memory");  // keep group counts aligned
    }

    MBAR_WAIT(dbar, 0u);
    asm volatile("tcgen05.fence::after_thread_sync;" ::: "memory");

    // ---- epilogue: warps 0-3 -> atom a (rows 0-127), 4-7 -> atom b ----
    int half = wid >> 2, rg = wid & 3;
    int grow = row0 + half * 128 + rg * 32 + lane;
    float sxw = g_xs * g_wsc;
    float ce  = g_xs * g_es;
    float xzpf = (float)g_xzpi;
    long long kzz = (long long)K * g_xzpi * g_wzpi;
    float rowcf = (float)((long long)g_wzpi * g_rsx[grow] - kzz);
    float amin = __int_as_float(0x7f800000), amax = -amin;
    uint32_t d1b = (uint32_t)(half * 128);
    uint32_t d2b = (uint32_t)(256 + half * 128);
    float* orow = out + (size_t)grow * N + col0;

    #pragma unroll 1
    for (int cc = 0; cc < 4; cc++) {
        uint32_t r1[32], r2[32];
        LDTM_X32(r1, tb + d1b + cc * 32);
        LDTM_X32(r2, tb + d2b + cc * 32);
        asm volatile("tcgen05.wait::ld.sync.aligned;" ::: "memory");
        int cbase = col0 + cc * 32;
        #pragma unroll
        for (int q = 0; q < 8; q++) {
            float ov[4];
            #pragma unroll
            for (int t = 0; t < 4; t++) {
                int j = q * 4 + t;
                int c = cbase + j;
                float v1 = __uint_as_float(r1[j]);
                float v2 = __uint_as_float(r2[j]);
                float br = v1 - rowcf - xzpf * (float)g_rsw[c];
                float op = br * sxw + bias[c];
                float act = op + ce * (v2 - xzpf * (float)g_rsqe[c]);
                amin = fminf(amin, act);
                amax = fmaxf(amax, act);
                ov[t] = op;
            }
            *(float4*)(orow + cc * 32 + q * 4) = make_float4(ov[0], ov[1], ov[2], ov[3]);
        }
    }

    #pragma unroll
    for (int o = 16; o > 0; o >>= 1) {
        amin = fminf(amin, __shfl_xor_sync(0xffffffffu, amin, o));
        amax = fmaxf(amax, __shfl_xor_sync(0xffffffffu, amax, o));
    }
    if (lane == 0) { red_min[wid] = amin; red_max[wid] = amax; }
    __syncthreads();
    if (tid == 0) {
        #pragma unroll
        for (int i = 1; i < 8; i++) { amin = fminf(amin, red_min[i]); amax = fmaxf(amax, red_max[i]); }
        atomicMin(&g_keys[4], fkey(amin));
        atomicMax(&g_keys[5], fkey(amax));
    }
    __syncthreads();
    if (wid == 0) {
        uint32_t nc = 512;
        asm volatile("tcgen05.dealloc.cta_group::1.sync.aligned.b32 %0, %1;"
                     :: "r"(tb), "r"(nc));
    }
#endif  // HAVE_TC
}

// ===========================================================================
// Engine B: mma.sync s8 fallback (baseline pass only) — round-2 proven kernel
// ===========================================================================
#define ASTRIDE 80

#if !HAVE_TC
__device__ __forceinline__ void cpa16g(void* smem, const void* gmem) {
    unsigned s = (unsigned)__cvta_generic_to_shared(smem);
    asm volatile("cp.async.cg.shared.global [%0], [%1], 16;\n" :: "r"(s), "l"(gmem));
}
__device__ __forceinline__ void mma_s8(int* d, const int* a, const int* b) {
    asm volatile(
        "mma.sync.aligned.m16n8k32.row.col.s32.s8.s8.s32 "
        "{%0,%1,%2,%3}, {%4,%5,%6,%7}, {%8,%9}, {%0,%1,%2,%3};\n"
        : "+r"(d[0]), "+r"(d[1]), "+r"(d[2]), "+r"(d[3])
        : "r"(a[0]), "r"(a[1]), "r"(a[2]), "r"(a[3]), "r"(b[0]), "r"(b[1]));
}
#endif

__global__ void __launch_bounds__(256) k_gemm_fb(const float* __restrict__ bias,
                                                 float* __restrict__ out,
                                                 int M, int N, int K) {
#if !HAVE_TC
    __shared__ __align__(16) signed char As[2][128 * ASTRIDE];
    __shared__ __align__(16) signed char Bw[2][64 * ASTRIDE];
    __shared__ __align__(16) signed char Be[2][64 * ASTRIDE];

    int tid = threadIdx.x;
    int wid = tid >> 5, lane = tid & 31;
    int wm = wid >> 1, wn = wid & 1;
    int g = lane >> 2, tig = lane & 3;
    int row0 = blockIdx.y << 7, col0 = blockIdx.x << 6;

    int acc1[2][4][4], acc2[2][4][4];
    #pragma unroll
    for (int i = 0; i < 2; i++)
        #pragma unroll
        for (int j = 0; j < 4; j++)
            #pragma unroll
            for (int c = 0; c < 4; c++) { acc1[i][j][c] = 0; acc2[i][j][c] = 0; }

    int nkt = K >> 6;
    int a_r0 = tid >> 2, a_c = (tid & 3) * 16;
    int b_r  = tid >> 2, b_c = (tid & 3) * 16;

    {
        const signed char* gA = g_qx + (size_t)(row0 + a_r0) * K + a_c;
        cpa16g(&As[0][a_r0 * ASTRIDE + a_c], gA);
        cpa16g(&As[0][(a_r0 + 64) * ASTRIDE + a_c], gA + (size_t)64 * K);
        cpa16g(&Bw[0][b_r * ASTRIDE + b_c], g_qw + (size_t)(col0 + b_r) * K + b_c);
        cpa16g(&Be[0][b_r * ASTRIDE + b_c], g_qe + (size_t)(col0 + b_r) * K + b_c);
        asm volatile("cp.async.commit_group;\n");
    }

    #pragma unroll 1
    for (int kt = 0; kt < nkt; kt++) {
        asm volatile("cp.async.wait_group 0;\n");
        __syncthreads();

        if (kt + 1 < nkt) {
            int b = (kt + 1) & 1;
            int k0 = (kt + 1) << 6;
            const signed char* gA = g_qx + (size_t)(row0 + a_r0) * K + k0 + a_c;
            cpa16g(&As[b][a_r0 * ASTRIDE + a_c], gA);
            cpa16g(&As[b][(a_r0 + 64) * ASTRIDE + a_c], gA + (size_t)64 * K);
            cpa16g(&Bw[b][b_r * ASTRIDE + b_c], g_qw + (size_t)(col0 + b_r) * K + k0 + b_c);
            cpa16g(&Be[b][b_r * ASTRIDE + b_c], g_qe + (size_t)(col0 + b_r) * K + k0 + b_c);
            asm volatile("cp.async.commit_group;\n");
        }

        const signed char* Ab  = As[kt & 1];
        const signed char* Bwb = Bw[kt & 1];
        const signed char* Beb = Be[kt & 1];

        #pragma unroll
        for (int kseg = 0; kseg < 2; kseg++) {
            int koff = kseg * 32 + tig * 4;
            int a[2][4];
            #pragma unroll
            for (int mi = 0; mi < 2; mi++) {
                int r0 = wm * 32 + mi * 16 + g;
                a[mi][0] = *(const int*)&Ab[r0 * ASTRIDE + koff];
                a[mi][1] = *(const int*)&Ab[(r0 + 8) * ASTRIDE + koff];
                a[mi][2] = *(const int*)&Ab[r0 * ASTRIDE + koff + 16];
                a[mi][3] = *(const int*)&Ab[(r0 + 8) * ASTRIDE + koff + 16];
            }
            int bw[4][2], be2[4][2];
            #pragma unroll
            for (int ni = 0; ni < 4; ni++) {
                int rn = wn * 32 + ni * 8 + g;
                bw[ni][0]  = *(const int*)&Bwb[rn * ASTRIDE + koff];
                bw[ni][1]  = *(const int*)&Bwb[rn * ASTRIDE + koff + 16];
                be2[ni][0] = *(const int*)&Beb[rn * ASTRIDE + koff];
                be2[ni][1] = *(const int*)&Beb[rn * ASTRIDE + koff + 16];
            }
            #pragma unroll
            for (int mi = 0; mi < 2; mi++)
                #pragma unroll
                for (int ni = 0; ni < 4; ni++) {
                    mma_s8(acc1[mi][ni], a[mi], bw[ni]);
                    mma_s8(acc2[mi][ni], a[mi], be2[ni]);
                }
        }
        __syncthreads();
    }

    float sxw = g_xs * g_wsc;
    float ce  = g_xs * g_es;
    int xzpi = g_xzpi, wzpi = g_wzpi;
    long long kzz = (long long)K * xzpi * wzpi;
    float amin = __int_as_float(0x7f800000), amax = -amin;

    int   rsw_[4][2], rsqe_[4][2];
    float bias_[4][2];
    int cbase[4];
    #pragma unroll
    for (int ni = 0; ni < 4; ni++) {
        int c0 = col0 + wn * 32 + ni * 8 + tig * 2;
        cbase[ni] = c0;
        rsw_[ni][0] = g_rsw[c0];  rsw_[ni][1] = g_rsw[c0 + 1];
        rsqe_[ni][0] = g_rsqe[c0]; rsqe_[ni][1] = g_rsqe[c0 + 1];
        float2 bv = *(const float2*)(bias + c0);
        bias_[ni][0] = bv.x; bias_[ni][1] = bv.y;
    }

    #pragma unroll
    for (int mi = 0; mi < 2; mi++) {
        #pragma unroll
        for (int rr = 0; rr < 2; rr++) {
            int row = row0 + wm * 32 + mi * 16 + rr * 8 + g;
            long long rowc = (long long)wzpi * g_rsx[row] - kzz;
            #pragma unroll
            for (int ni = 0; ni < 4; ni++) {
                float ov[2];
                #pragma unroll
                for (int cc = 0; cc < 2; cc++) {
                    int v1 = acc1[mi][ni][rr * 2 + cc];
                    int v2 = acc2[mi][ni][rr * 2 + cc];
                    long long br = (long long)v1 - rowc - (long long)xzpi * rsw_[ni][cc];
                    float op = (float)br * sxw + bias_[ni][cc];
                    float act = op + ce * (float)((long long)v2 - (long long)xzpi * rsqe_[ni][cc]);
                    amin = fminf(amin, act);
                    amax = fmaxf(amax, act);
                    ov[cc] = op;
                }
                *(float2*)(out + (size_t)row * N + cbase[ni]) = make_float2(ov[0], ov[1]);
            }
        }
    }

    #pragma unroll
    for (int o = 16; o > 0; o >>= 1) {
        amin = fminf(amin, __shfl_xor_sync(0xffffffffu, amin, o));
        amax = fmaxf(amax, __shfl_xor_sync(0xffffffffu, amax, o));
    }
    __shared__ float smin[8], smax[8];
    if (lane == 0) { smin[wid] = amin; smax[wid] = amax; }
    __syncthreads();
    if (tid == 0) {
        #pragma unroll
        for (int i = 1; i < 8; i++) { amin = fminf(amin, smin[i]); amax = fmaxf(amax, smax[i]); }
        atomicMin(&g_keys[4], fkey(amin));
        atomicMax(&g_keys[5], fkey(amax));
    }
#endif  // !HAVE_TC
}

__global__ void k_scales2() {
    float amin = fdec(g_keys[4]), amax = fdec(g_keys[5]);
    float as = (amax - amin) / 255.0f;
    g_as = as;
    g_azp = rintf(0.0f - amin / as);
}

__global__ void k_requant(float* __restrict__ out, long long n4) {
    float as = g_as, azp = g_azp;
    float4* p = (float4*)out;
    for (long long i = blockIdx.x * (long long)blockDim.x + threadIdx.x; i < n4;
         i += (long long)gridDim.x * blockDim.x) {
        float4 v = p[i];
        v.x = (fminf(255.f, fmaxf(0.f, rintf(v.x / as + azp))) - azp) * as;
        v.y = (fminf(255.f, fmaxf(0.f, rintf(v.y / as + azp))) - azp) * as;
        v.z = (fminf(255.f, fmaxf(0.f, rintf(v.z / as + azp))) - azp) * as;
        v.w = (fminf(255.f, fmaxf(0.f, rintf(v.w / as + azp))) - azp) * as;
        p[i] = v;
    }
}

extern "C" void kernel_launch(void* const* d_in, const int* in_sizes, int n_in,
                              void* d_out, int out_size) {
    const float* x = (const float*)d_in[0];
    const float* w = (const float*)d_in[1];
    const float* b = (const float*)d_in[2];
    float* out = (float*)d_out;

    int N = in_sizes[2];
    int K = in_sizes[1] / N;
    int M = in_sizes[0] / K;
    if (M > MAXM || N > MAXN || K > MAXK) return;
    if ((M & 255) || (N & 127) || (K & 127)) return;

    cudaFuncSetAttribute(k_gemm_tc, cudaFuncAttributeMaxDynamicSharedMemorySize, SMEM_TC);

    k_init<<<1, 32>>>();
    k_minmax<<<864, 256>>>(x, (long long)M * K / 4, 0, 1);
    k_minmax<<<864, 256>>>(w, (long long)N * K / 4, 2, 3);
    k_scales1<<<1, 1>>>();
    k_quant_x<<<M, 256>>>(x, K);
    k_quant_w<<<N, 256>>>(w, K);

    dim3 grid_tc(N / 128, M / 256);
    k_gemm_tc<<<grid_tc, 256, SMEM_TC>>>(b, out, M, N, K);
    dim3 grid_fb(N / 64, M / 128);
    k_gemm_fb<<<grid_fb, 256>>>(b, out, M, N, K);

    k_scales2<<<1, 1>>>();
    k_requant<<<4096, 256>>>(out, (long long)M * N / 4);
}